// round 2
// baseline (speedup 1.0000x reference)
#include <cuda_runtime.h>
#include <math.h>

// Problem constants
#define B_   8
#define L_   8192
#define D_   512
#define H_   8
#define DH_  64
#define D3_  1536
#define M_   (B_ * L_)      // 65536 rows
#define EPS_ 1e-6f
#define NSC  16             // s-chunks for kv partial sums
#define SCHUNK (L_ / NSC)   // 512

// ---------------------------------------------------------------------------
// Scratch (static __device__ globals; no allocations anywhere)
// ---------------------------------------------------------------------------
__device__ float g_X  [M_ * D3_];        // concat(q,k,v)            402 MB
__device__ float g_QKV[M_ * D3_];        // qkv projection output    402 MB
__device__ float g_ATT[M_ * D_];         // attention output         134 MB
__device__ float g_KVP[NSC * B_ * H_ * DH_ * DH_]; // kv partials    16 MB
__device__ float g_KSP[NSC * B_ * H_ * DH_];       // ksum partials
__device__ float g_KV [B_ * H_ * DH_ * DH_];
__device__ float g_KS [B_ * H_ * DH_];

// ---------------------------------------------------------------------------
// 1) Concat q,k,v -> X [M, 1536]  (float4 throughout)
// ---------------------------------------------------------------------------
__global__ void concat_k(const float4* __restrict__ q,
                         const float4* __restrict__ k,
                         const float4* __restrict__ v) {
    int i = blockIdx.x * 256 + threadIdx.x;     // exactly M_*128 threads
    int n = i >> 7;
    int c = i & 127;
    float4* X = reinterpret_cast<float4*>(g_X);
    size_t base = (size_t)n * 384;
    X[base + c]       = q[i];
    X[base + 128 + c] = k[i];
    X[base + 256 + c] = v[i];
}

// ---------------------------------------------------------------------------
// 2) SGEMM (NT): C[M,N] = A[M,K] @ B[N,K]^T (+ optional bias[N])
//    128x128 block tile, BK=16, 256 threads, 8x8 per-thread microtile.
//    Requires M%128==0, N%128==0, K%16==0 (true for all uses here).
// ---------------------------------------------------------------------------
__global__ __launch_bounds__(256)
void sgemm_nt(const float* __restrict__ A, const float* __restrict__ Bm,
              const float* __restrict__ bias, float* __restrict__ C,
              int N, int K) {
    __shared__ float As[16][128];
    __shared__ float Bs[16][128];

    const int tid = threadIdx.x;
    const int tx  = tid & 15;
    const int ty  = tid >> 4;

    const float* Ab = A  + (size_t)blockIdx.y * 128 * K;
    const float* Bb = Bm + (size_t)blockIdx.x * 128 * K;

    float acc[8][8] = {};

    for (int k0 = 0; k0 < K; k0 += 16) {
        #pragma unroll
        for (int i = 0; i < 2; i++) {
            int idx = tid + i * 256;
            int row = idx >> 2;
            int c4  = (idx & 3) * 4;
            float4 va = *reinterpret_cast<const float4*>(Ab + (size_t)row * K + k0 + c4);
            As[c4 + 0][row] = va.x; As[c4 + 1][row] = va.y;
            As[c4 + 2][row] = va.z; As[c4 + 3][row] = va.w;
            float4 vb = *reinterpret_cast<const float4*>(Bb + (size_t)row * K + k0 + c4);
            Bs[c4 + 0][row] = vb.x; Bs[c4 + 1][row] = vb.y;
            Bs[c4 + 2][row] = vb.z; Bs[c4 + 3][row] = vb.w;
        }
        __syncthreads();

        #pragma unroll
        for (int kk = 0; kk < 16; kk++) {
            float ar[8], br[8];
            *reinterpret_cast<float4*>(&ar[0]) = *reinterpret_cast<const float4*>(&As[kk][ty * 8]);
            *reinterpret_cast<float4*>(&ar[4]) = *reinterpret_cast<const float4*>(&As[kk][ty * 8 + 4]);
            *reinterpret_cast<float4*>(&br[0]) = *reinterpret_cast<const float4*>(&Bs[kk][tx * 8]);
            *reinterpret_cast<float4*>(&br[4]) = *reinterpret_cast<const float4*>(&Bs[kk][tx * 8 + 4]);
            #pragma unroll
            for (int i = 0; i < 8; i++)
                #pragma unroll
                for (int j = 0; j < 8; j++)
                    acc[i][j] = fmaf(ar[i], br[j], acc[i][j]);
        }
        __syncthreads();
    }

    const int rowb = blockIdx.y * 128 + ty * 8;
    const int colb = blockIdx.x * 128 + tx * 8;
    float bv[8];
    #pragma unroll
    for (int j = 0; j < 8; j++) bv[j] = bias ? bias[colb + j] : 0.0f;

    #pragma unroll
    for (int i = 0; i < 8; i++) {
        float4 o0, o1;
        o0.x = acc[i][0] + bv[0]; o0.y = acc[i][1] + bv[1];
        o0.z = acc[i][2] + bv[2]; o0.w = acc[i][3] + bv[3];
        o1.x = acc[i][4] + bv[4]; o1.y = acc[i][5] + bv[5];
        o1.z = acc[i][6] + bv[6]; o1.w = acc[i][7] + bv[7];
        float* cp = C + (size_t)(rowb + i) * N + colb;
        *reinterpret_cast<float4*>(cp)     = o0;
        *reinterpret_cast<float4*>(cp + 4) = o1;
    }
}

// ---------------------------------------------------------------------------
// 3) elu+1 feature map on q & k parts of QKV (cols [0,1024) of each row)
// ---------------------------------------------------------------------------
__device__ __forceinline__ float elu1(float x) {
    return x > 0.0f ? x + 1.0f : expf(x);
}

__global__ void elu_k() {
    int i = blockIdx.x * 256 + threadIdx.x;     // exactly M_*256 threads
    int n = i >> 8;
    int c = i & 255;                            // 256 float4 = cols [0,1024)
    float4* Q = reinterpret_cast<float4*>(g_QKV);
    size_t idx = (size_t)n * 384 + c;
    float4 v = Q[idx];
    v.x = elu1(v.x); v.y = elu1(v.y); v.z = elu1(v.z); v.w = elu1(v.w);
    Q[idx] = v;
}

// ---------------------------------------------------------------------------
// 4) kv state partials: for each (b,h,sc):
//    KVP[sc,bh,m,d] = sum_{s in chunk} k[s,d] * v[s,m]
//    KSP[sc,bh,d]   = sum_{s in chunk} k[s,d]
//    Deterministic (no atomics) -> graph replays are bit-stable.
// ---------------------------------------------------------------------------
__global__ __launch_bounds__(256)
void kv_kernel() {
    __shared__ float ks[16][64];
    __shared__ float vs[16][64];

    const int bh = blockIdx.x;   // 0..63
    const int sc = blockIdx.y;   // 0..15
    const int b  = bh >> 3;
    const int h  = bh & 7;
    const int tid = threadIdx.x;
    const int tx  = tid & 15;
    const int ty  = tid >> 4;
    const int lrow = tid >> 4;           // 0..15
    const int lc   = (tid & 15) * 4;     // 0..60

    float acc[4][4] = {};
    float ksa[4] = {0.f, 0.f, 0.f, 0.f};

    const size_t rowbase = ((size_t)b * L_ + (size_t)sc * SCHUNK) * D3_;
    const float* kp = g_QKV + rowbase + D_     + h * DH_;
    const float* vp = g_QKV + rowbase + 2 * D_ + h * DH_;

    for (int it = 0; it < SCHUNK; it += 16) {
        size_t off = (size_t)(it + lrow) * D3_ + lc;
        *reinterpret_cast<float4*>(&ks[lrow][lc]) = *reinterpret_cast<const float4*>(kp + off);
        *reinterpret_cast<float4*>(&vs[lrow][lc]) = *reinterpret_cast<const float4*>(vp + off);
        __syncthreads();

        #pragma unroll
        for (int ss = 0; ss < 16; ss++) {
            float kr[4], vr[4];
            *reinterpret_cast<float4*>(kr) = *reinterpret_cast<const float4*>(&ks[ss][tx * 4]);
            *reinterpret_cast<float4*>(vr) = *reinterpret_cast<const float4*>(&vs[ss][ty * 4]);
            #pragma unroll
            for (int i = 0; i < 4; i++)
                #pragma unroll
                for (int j = 0; j < 4; j++)
                    acc[i][j] = fmaf(vr[i], kr[j], acc[i][j]);
            if (ty == 0) {
                #pragma unroll
                for (int j = 0; j < 4; j++) ksa[j] += kr[j];
            }
        }
        __syncthreads();
    }

    float* kvp = g_KVP + ((size_t)sc * 64 + bh) * 4096;
    #pragma unroll
    for (int i = 0; i < 4; i++)
        #pragma unroll
        for (int j = 0; j < 4; j++)
            kvp[(ty * 4 + i) * 64 + tx * 4 + j] = acc[i][j];

    if (ty == 0) {
        float* ksp = g_KSP + ((size_t)sc * 64 + bh) * 64 + tx * 4;
        #pragma unroll
        for (int j = 0; j < 4; j++) ksp[j] = ksa[j];
    }
}

// ---------------------------------------------------------------------------
// 5) Reduce partials -> KV, KS
// ---------------------------------------------------------------------------
__global__ void kv_reduce() {
    int i = blockIdx.x * 256 + threadIdx.x;     // 266240 threads (exact)
    if (i < 262144) {
        float s = 0.f;
        #pragma unroll
        for (int sc = 0; sc < NSC; sc++) s += g_KVP[sc * 262144 + i];
        g_KV[i] = s;
    } else {
        int j = i - 262144;                     // 0..4095
        float s = 0.f;
        #pragma unroll
        for (int sc = 0; sc < NSC; sc++) s += g_KSP[sc * 4096 + j];
        g_KS[j] = s;
    }
}

// ---------------------------------------------------------------------------
// 6) Attention apply: out[l,h,m] = z * sum_d q[l,h,d] * KV[h][m,d]
//    z = 1 / (sum_d q[d] * KS[d] + eps)
// ---------------------------------------------------------------------------
__global__ __launch_bounds__(256)
void attn_k() {
    __shared__ float kvs[64][65];   // padded: bank-conflict-free row access
    __shared__ float kss[64];

    const int bh  = blockIdx.x;     // 0..63
    const int lch = blockIdx.y;     // 0..7
    const int b = bh >> 3;
    const int h = bh & 7;
    const int tid = threadIdx.x;

    for (int i = tid; i < 4096; i += 256)
        kvs[i >> 6][i & 63] = g_KV[(size_t)bh * 4096 + i];
    if (tid < 64) kss[tid] = g_KS[bh * 64 + tid];
    __syncthreads();

    const int wid  = tid >> 5;
    const int lane = tid & 31;
    const float ks0 = kss[lane];
    const float ks1 = kss[lane + 32];

    for (int r = lch * 1024 + wid; r < (lch + 1) * 1024; r += 8) {
        size_t qoff = ((size_t)b * L_ + r) * D3_ + h * DH_;
        float q0 = g_QKV[qoff + lane];
        float q1 = g_QKV[qoff + lane + 32];

        float p = q0 * ks0 + q1 * ks1;
        #pragma unroll
        for (int o = 16; o > 0; o >>= 1) p += __shfl_xor_sync(0xffffffffu, p, o);
        float z = 1.0f / (p + EPS_);

        float a0 = 0.f, a1 = 0.f;
        #pragma unroll
        for (int d = 0; d < 32; d++) {
            float qd = __shfl_sync(0xffffffffu, q0, d);
            a0 = fmaf(qd, kvs[lane][d], a0);
            a1 = fmaf(qd, kvs[lane + 32][d], a1);
        }
        #pragma unroll
        for (int d = 0; d < 32; d++) {
            float qd = __shfl_sync(0xffffffffu, q1, d);
            a0 = fmaf(qd, kvs[lane][d + 32], a0);
            a1 = fmaf(qd, kvs[lane + 32][d + 32], a1);
        }

        size_t ooff = ((size_t)b * L_ + r) * D_ + h * DH_;
        g_ATT[ooff + lane]      = a0 * z;
        g_ATT[ooff + lane + 32] = a1 * z;
    }
}

// ---------------------------------------------------------------------------
// Launch
// ---------------------------------------------------------------------------
extern "C" void kernel_launch(void* const* d_in, const int* in_sizes, int n_in,
                              void* d_out, int out_size) {
    const float* q     = (const float*)d_in[0];
    const float* k     = (const float*)d_in[1];
    const float* v     = (const float*)d_in[2];
    const float* w_qkv = (const float*)d_in[3];
    const float* w_out = (const float*)d_in[4];
    const float* b_out = (const float*)d_in[5];
    float* out = (float*)d_out;

    float *X, *QKV, *ATT;
    cudaGetSymbolAddress((void**)&X,   g_X);
    cudaGetSymbolAddress((void**)&QKV, g_QKV);
    cudaGetSymbolAddress((void**)&ATT, g_ATT);

    // 1) concat -> X
    concat_k<<<32768, 256>>>((const float4*)q, (const float4*)k, (const float4*)v);
    // 2) QKV = X @ W_qkv^T     (M=65536, N=1536, K=1536)
    sgemm_nt<<<dim3(12, 512), 256>>>(X, w_qkv, nullptr, QKV, 1536, 1536);
    // 3) elu+1 on q,k parts
    elu_k<<<65536, 256>>>();
    // 4) kv-state partials, 5) reduce
    kv_kernel<<<dim3(64, NSC), 256>>>();
    kv_reduce<<<1040, 256>>>();
    // 6) apply attention
    attn_k<<<dim3(64, 8), 256>>>();
    // 7) out = ATT @ W_out^T + b_out   (M=65536, N=512, K=512)
    sgemm_nt<<<dim3(4, 512), 256>>>(ATT, w_out, b_out, out, 512, 512);
}

// round 4
// speedup vs baseline: 4.7777x; 4.7777x over previous
#include <cuda_runtime.h>
#include <cuda_fp16.h>
#include <math.h>
#include <stdint.h>

#define B_   8
#define L_   8192
#define D_   512
#define H_   8
#define D3_  1536
#define M_   (B_ * L_)
#define EPS_ 1e-6f
#define NSC  16
#define SCHUNK (L_ / NSC)

// ---------------------------------------------------------------------------
// Scratch
// ---------------------------------------------------------------------------
__device__ __half g_A1 [(size_t)M_ * D3_];    // concat(q,k,v) fp16
__device__ __half g_W1 [(size_t)D3_ * D3_];
__device__ float  g_QKV[(size_t)M_ * D3_];
__device__ __half g_A2 [(size_t)M_ * D_];     // attention out fp16
__device__ __half g_W2 [(size_t)D_ * D_];
__device__ float g_KVP[NSC * 64 * 64 * 64];
__device__ float g_KSP[NSC * 64 * 64];
__device__ float g_KV [64 * 64 * 64];
__device__ float g_KS [64 * 64];

// ---------------------------------------------------------------------------
// PTX helpers (all valid on family-common sm_103 target: >= sm_80 features)
// ---------------------------------------------------------------------------
__device__ __forceinline__ void cp16(uint32_t dst, const void* src) {
    asm volatile("cp.async.cg.shared.global [%0], [%1], 16;" :: "r"(dst), "l"(src) : "memory");
}
__device__ __forceinline__ void cp_commit() {
    asm volatile("cp.async.commit_group;" ::: "memory");
}
template <int N>
__device__ __forceinline__ void cp_wait() {
    asm volatile("cp.async.wait_group %0;" :: "n"(N) : "memory");
}
__device__ __forceinline__ void ldsm4(uint32_t& r0, uint32_t& r1, uint32_t& r2, uint32_t& r3,
                                      uint32_t addr) {
    asm volatile("ldmatrix.sync.aligned.m8n8.x4.shared.b16 {%0,%1,%2,%3}, [%4];"
                 : "=r"(r0), "=r"(r1), "=r"(r2), "=r"(r3) : "r"(addr));
}
__device__ __forceinline__ void mma16816(float* d, const uint32_t* a, uint32_t b0, uint32_t b1) {
    asm volatile(
        "mma.sync.aligned.m16n8k16.row.col.f32.f16.f16.f32 "
        "{%0,%1,%2,%3}, {%4,%5,%6,%7}, {%8,%9}, {%0,%1,%2,%3};"
        : "+f"(d[0]), "+f"(d[1]), "+f"(d[2]), "+f"(d[3])
        : "r"(a[0]), "r"(a[1]), "r"(a[2]), "r"(a[3]), "r"(b0), "r"(b1));
}
__device__ __forceinline__ float elu1(float x) {
    return x > 0.0f ? x + 1.0f : expf(x);
}

// ---------------------------------------------------------------------------
// HMMA GEMM: C[M,Nout](fp32) = A[M,K](fp16) @ Bw[Nout,K](fp16)^T
// CTA tile 128x128, BK=32, 4-stage cp.async, 8 warps (4m x 2n), warp 32x64.
// Smem rows padded to 80B -> conflict-free ldmatrix.
// mode 0: elu+1 where global col < 1024.  mode 1: += bias[col].
// ---------------------------------------------------------------------------
#define STAGES 4
#define ROWB   80u
#define TILEB  (128u * ROWB)     // 10240
#define STGB   (2u * TILEB)      // 20480
#define GSMEM  (STAGES * STGB)   // 81920

__global__ void __launch_bounds__(256, 2)
gemm_h(const __half* __restrict__ A, const __half* __restrict__ Bw,
       float* __restrict__ C, const float* __restrict__ bias,
       int K, int NT, int Nout, int mode)
{
    extern __shared__ char smem[];
    const uint32_t sb = (uint32_t)__cvta_generic_to_shared(smem);
    const int tid = threadIdx.x;
    const int w = tid >> 5, lane = tid & 31;
    const int mt = blockIdx.x / NT, nt = blockIdx.x % NT;
    const int wm = w & 3, wn = w >> 2;
    const int ktiles = K >> 5;

    const __half* Ab = A  + (size_t)(mt * 128) * K;
    const __half* Bb = Bw + (size_t)(nt * 128) * K;

    // per-thread cp.async chunk mapping: 512 chunks per tile, 2 per thread
    const int r0c = tid >> 2,              c0c = tid & 3;
    const int r1c = (tid + 256) >> 2,      c1c = c0c;

    // ldmatrix lane offsets
    const uint32_t aoff = (uint32_t)(wm * 32 + (lane & 15)) * ROWB + (uint32_t)(lane >> 4) * 16;
    const uint32_t boff = TILEB +
        (uint32_t)(wn * 64 + ((lane >> 4) << 3) + (lane & 7)) * ROWB +
        (uint32_t)((lane >> 3) & 1) * 16;

    float acc[2][8][4];
    #pragma unroll
    for (int i = 0; i < 2; i++)
        #pragma unroll
        for (int j = 0; j < 8; j++)
            #pragma unroll
            for (int q = 0; q < 4; q++) acc[i][j][q] = 0.0f;

    auto load_stage = [&](int kt) {
        uint32_t base = sb + (uint32_t)(kt & (STAGES - 1)) * STGB;
        int k0 = kt * 32;
        cp16(base + r0c * ROWB + c0c * 16,         Ab + (size_t)r0c * K + k0 + c0c * 8);
        cp16(base + r1c * ROWB + c1c * 16,         Ab + (size_t)r1c * K + k0 + c1c * 8);
        cp16(base + TILEB + r0c * ROWB + c0c * 16, Bb + (size_t)r0c * K + k0 + c0c * 8);
        cp16(base + TILEB + r1c * ROWB + c1c * 16, Bb + (size_t)r1c * K + k0 + c1c * 8);
        cp_commit();
    };

    load_stage(0);
    load_stage(1);
    load_stage(2);

    for (int kt = 0; kt < ktiles; kt++) {
        cp_wait<STAGES - 2>();
        __syncthreads();
        if (kt + STAGES - 1 < ktiles) load_stage(kt + STAGES - 1);
        else cp_commit();

        uint32_t base = sb + (uint32_t)(kt & (STAGES - 1)) * STGB;
        #pragma unroll
        for (int s = 0; s < 2; s++) {
            uint32_t a[2][4], b[4][4];
            ldsm4(a[0][0], a[0][1], a[0][2], a[0][3], base + aoff + s * 32);
            ldsm4(a[1][0], a[1][1], a[1][2], a[1][3], base + aoff + 16 * ROWB + s * 32);
            #pragma unroll
            for (int nb = 0; nb < 4; nb++)
                ldsm4(b[nb][0], b[nb][1], b[nb][2], b[nb][3],
                      base + boff + (uint32_t)nb * 16 * ROWB + s * 32);
            #pragma unroll
            for (int mi = 0; mi < 2; mi++)
                #pragma unroll
                for (int ni = 0; ni < 8; ni++)
                    mma16816(acc[mi][ni], a[mi],
                             b[ni >> 1][(ni & 1) * 2], b[ni >> 1][(ni & 1) * 2 + 1]);
        }
    }

    // Epilogue: direct reg -> gmem (float2 per 8x8 sub-row)
    const int mrow = mt * 128 + wm * 32 + (lane >> 2);
    const int ncol = nt * 128 + wn * 64 + (lane & 3) * 2;
    #pragma unroll
    for (int mi = 0; mi < 2; mi++) {
        #pragma unroll
        for (int ni = 0; ni < 8; ni++) {
            int col = ncol + ni * 8;
            float x0 = acc[mi][ni][0], x1 = acc[mi][ni][1];
            float x2 = acc[mi][ni][2], x3 = acc[mi][ni][3];
            if (mode == 0) {
                if (col < 1024)     { x0 = elu1(x0); x2 = elu1(x2); }
                if (col + 1 < 1024) { x1 = elu1(x1); x3 = elu1(x3); }
            } else {
                float bv0 = bias[col], bv1 = bias[col + 1];
                x0 += bv0; x1 += bv1; x2 += bv0; x3 += bv1;
            }
            int row = mrow + mi * 16;
            float2* p0 = reinterpret_cast<float2*>(C + (size_t)row * Nout + col);
            float2* p1 = reinterpret_cast<float2*>(C + (size_t)(row + 8) * Nout + col);
            *p0 = make_float2(x0, x1);
            *p1 = make_float2(x2, x3);
        }
    }
}

// ---------------------------------------------------------------------------
// Conversions fp32 -> fp16
// ---------------------------------------------------------------------------
__device__ __forceinline__ uint2 pack4h(float4 s) {
    __half2 h0 = __floats2half2_rn(s.x, s.y);
    __half2 h1 = __floats2half2_rn(s.z, s.w);
    uint2 r;
    r.x = *reinterpret_cast<uint32_t*>(&h0);
    r.y = *reinterpret_cast<uint32_t*>(&h1);
    return r;
}

__global__ void conv1_k(const float4* __restrict__ q, const float4* __restrict__ k,
                        const float4* __restrict__ v) {
    int i = blockIdx.x * 256 + threadIdx.x;   // exactly M_*384
    int n = i / 384, c4 = i % 384;
    float4 s = (c4 < 128) ? q[(size_t)n * 128 + c4]
             : (c4 < 256) ? k[(size_t)n * 128 + (c4 - 128)]
                          : v[(size_t)n * 128 + (c4 - 256)];
    *reinterpret_cast<uint2*>(g_A1 + (size_t)n * D3_ + c4 * 4) = pack4h(s);
}

__global__ void convw_k(const float* __restrict__ W, __half* __restrict__ Wd) {
    int i = blockIdx.x * 256 + threadIdx.x;   // rows*K/4 threads exact
    float4 s = reinterpret_cast<const float4*>(W)[i];
    *reinterpret_cast<uint2*>(Wd + (size_t)i * 4) = pack4h(s);
}

// ---------------------------------------------------------------------------
// kv state partials + reduce (fp32, deterministic)
// ---------------------------------------------------------------------------
__global__ __launch_bounds__(256)
void kv_kernel() {
    __shared__ float ks[16][64];
    __shared__ float vs[16][64];

    const int bh = blockIdx.x, sc = blockIdx.y;
    const int b = bh >> 3, h = bh & 7;
    const int tid = threadIdx.x;
    const int tx = tid & 15, ty = tid >> 4;
    const int lrow = tid >> 4, lc = (tid & 15) * 4;

    float acc[4][4] = {};
    float ksa[4] = {0.f, 0.f, 0.f, 0.f};

    const size_t rowbase = ((size_t)b * L_ + (size_t)sc * SCHUNK) * D3_;
    const float* kp = g_QKV + rowbase + D_ + h * 64;
    const float* vp = g_QKV + rowbase + 2 * D_ + h * 64;

    for (int it = 0; it < SCHUNK; it += 16) {
        size_t off = (size_t)(it + lrow) * D3_ + lc;
        *reinterpret_cast<float4*>(&ks[lrow][lc]) = *reinterpret_cast<const float4*>(kp + off);
        *reinterpret_cast<float4*>(&vs[lrow][lc]) = *reinterpret_cast<const float4*>(vp + off);
        __syncthreads();
        #pragma unroll
        for (int ss = 0; ss < 16; ss++) {
            float kr[4], vr[4];
            *reinterpret_cast<float4*>(kr) = *reinterpret_cast<const float4*>(&ks[ss][tx * 4]);
            *reinterpret_cast<float4*>(vr) = *reinterpret_cast<const float4*>(&vs[ss][ty * 4]);
            #pragma unroll
            for (int i = 0; i < 4; i++)
                #pragma unroll
                for (int j = 0; j < 4; j++)
                    acc[i][j] = fmaf(vr[i], kr[j], acc[i][j]);
            if (ty == 0) {
                #pragma unroll
                for (int j = 0; j < 4; j++) ksa[j] += kr[j];
            }
        }
        __syncthreads();
    }

    float* kvp = g_KVP + ((size_t)sc * 64 + bh) * 4096;
    #pragma unroll
    for (int i = 0; i < 4; i++)
        #pragma unroll
        for (int j = 0; j < 4; j++)
            kvp[(ty * 4 + i) * 64 + tx * 4 + j] = acc[i][j];
    if (ty == 0) {
        float* ksp = g_KSP + ((size_t)sc * 64 + bh) * 64 + tx * 4;
        #pragma unroll
        for (int j = 0; j < 4; j++) ksp[j] = ksa[j];
    }
}

__global__ void kv_reduce() {
    int i = blockIdx.x * 256 + threadIdx.x;
    if (i < 262144) {
        float s = 0.f;
        #pragma unroll
        for (int sc = 0; sc < NSC; sc++) s += g_KVP[sc * 262144 + i];
        g_KV[i] = s;
    } else {
        int j = i - 262144;
        float s = 0.f;
        #pragma unroll
        for (int sc = 0; sc < NSC; sc++) s += g_KSP[sc * 4096 + j];
        g_KS[j] = s;
    }
}

// ---------------------------------------------------------------------------
// Attention apply -> writes g_A2 (fp16)
// ---------------------------------------------------------------------------
__global__ __launch_bounds__(256)
void attn_k() {
    __shared__ float kvs[64][65];
    __shared__ float kss[64];

    const int bh = blockIdx.x, lch = blockIdx.y;
    const int b = bh >> 3, h = bh & 7;
    const int tid = threadIdx.x;

    for (int i = tid; i < 4096; i += 256)
        kvs[i >> 6][i & 63] = g_KV[(size_t)bh * 4096 + i];
    if (tid < 64) kss[tid] = g_KS[bh * 64 + tid];
    __syncthreads();

    const int wid = tid >> 5, lane = tid & 31;
    const float ks0 = kss[lane];
    const float ks1 = kss[lane + 32];

    for (int r = lch * 1024 + wid; r < (lch + 1) * 1024; r += 8) {
        size_t qoff = ((size_t)b * L_ + r) * D3_ + h * 64;
        float q0 = g_QKV[qoff + lane];
        float q1 = g_QKV[qoff + lane + 32];

        float p = q0 * ks0 + q1 * ks1;
        #pragma unroll
        for (int o = 16; o > 0; o >>= 1) p += __shfl_xor_sync(0xffffffffu, p, o);
        float z = 1.0f / (p + EPS_);

        float a0 = 0.f, a1 = 0.f;
        #pragma unroll
        for (int d = 0; d < 32; d++) {
            float qd = __shfl_sync(0xffffffffu, q0, d);
            a0 = fmaf(qd, kvs[lane][d], a0);
            a1 = fmaf(qd, kvs[lane + 32][d], a1);
        }
        #pragma unroll
        for (int d = 0; d < 32; d++) {
            float qd = __shfl_sync(0xffffffffu, q1, d);
            a0 = fmaf(qd, kvs[lane][d + 32], a0);
            a1 = fmaf(qd, kvs[lane + 32][d + 32], a1);
        }

        __half* row = g_A2 + ((size_t)b * L_ + r) * D_ + h * 64;
        row[lane]      = __float2half(a0 * z);
        row[lane + 32] = __float2half(a1 * z);
    }
}

// ---------------------------------------------------------------------------
// Launch
// ---------------------------------------------------------------------------
extern "C" void kernel_launch(void* const* d_in, const int* in_sizes, int n_in,
                              void* d_out, int out_size) {
    const float* q     = (const float*)d_in[0];
    const float* k     = (const float*)d_in[1];
    const float* v     = (const float*)d_in[2];
    const float* w_qkv = (const float*)d_in[3];
    const float* w_out = (const float*)d_in[4];
    const float* b_out = (const float*)d_in[5];
    float* out = (float*)d_out;

    __half *A1, *W1, *A2, *W2;
    float *QKV;
    cudaGetSymbolAddress((void**)&A1,  g_A1);
    cudaGetSymbolAddress((void**)&W1,  g_W1);
    cudaGetSymbolAddress((void**)&A2,  g_A2);
    cudaGetSymbolAddress((void**)&W2,  g_W2);
    cudaGetSymbolAddress((void**)&QKV, g_QKV);

    static int smem_set = 0;
    if (!smem_set) {
        cudaFuncSetAttribute(gemm_h, cudaFuncAttributeMaxDynamicSharedMemorySize, GSMEM);
        smem_set = 1;
    }

    // 1) fp16 conversions
    conv1_k<<<98304, 256>>>((const float4*)q, (const float4*)k, (const float4*)v);
    convw_k<<<2304, 256>>>(w_qkv, W1);   // 1536*1536/4 / 256
    convw_k<<<256, 256>>>(w_out, W2);    // 512*512/4 / 256

    // 2) QKV = X @ W_qkv^T (M=65536, N=1536, K=1536), fused elu on cols<1024
    gemm_h<<<512 * 12, 256, GSMEM>>>(A1, W1, QKV, nullptr, 1536, 12, 1536, 0);

    // 3) kv state + reduce + attention apply (writes A2 fp16)
    kv_kernel<<<dim3(64, NSC), 256>>>();
    kv_reduce<<<1040, 256>>>();
    attn_k<<<dim3(64, 8), 256>>>();

    // 4) out = ATT @ W_out^T + b_out (M=65536, N=512, K=512)
    gemm_h<<<512 * 4, 256, GSMEM>>>(A2, W2, out, b_out, 512, 4, 512, 1);
}